// round 15
// baseline (speedup 1.0000x reference)
#include <cuda_runtime.h>
#include <cuda_bf16.h>

#define FULLMASK 0xFFFFFFFFu
#define LOG2E 1.4426950408889634f

using u64 = unsigned long long;

__device__ __forceinline__ u64 fma2(u64 a, u64 b, u64 c) {
    u64 d; asm("fma.rn.f32x2 %0,%1,%2,%3;" : "=l"(d) : "l"(a), "l"(b), "l"(c)); return d;
}
__device__ __forceinline__ u64 add2(u64 a, u64 b) {
    u64 d; asm("add.rn.f32x2 %0,%1,%2;" : "=l"(d) : "l"(a), "l"(b)); return d;
}
__device__ __forceinline__ u64 bcast2(float v) {
    u64 d; asm("mov.b64 %0,{%1,%1};" : "=l"(d) : "f"(v)); return d;
}
__device__ __forceinline__ float2 unpk(u64 v) {
    float2 r; asm("mov.b64 {%0,%1},%2;" : "=f"(r.x), "=f"(r.y) : "l"(v)); return r;
}
__device__ __forceinline__ float ex2f(float x) {
    float r; asm("ex2.approx.f32 %0,%1;" : "=f"(r) : "f"(x)); return r;
}
__device__ __forceinline__ float rcpf(float x) {
    float r; asm("rcp.approx.f32 %0,%1;" : "=f"(r) : "f"(x)); return r;
}
__device__ __forceinline__ float rsqf(float x) {
    float r; asm("rsqrt.approx.f32 %0,%1;" : "=f"(r) : "f"(x)); return r;
}

union Row { ulonglong2 u; float4 f; };

// Layout: 4 locations per warp, 8 lanes per location.
// t=lane&7, h=t>>2 (row-half), q=t&3 (d-quad). Lane holds the 8 rows of its
// half in XOR ORDER: slot (k,j), k=0..3, j=0..1 -> row i = 8h + 2*(q^k) + j,
// columns d = 4q..4q+3. Lane OWNS rows 8h+2q, 8h+2q+1 (logits bb0/bb1).
// Both directions of quad communication are shfl.xor (width 4, involutive):
//   e-gather:      e[2k+j] = shfl_xor(e_j, k)
//   agree reduce:  p_j    += shfl_xor(pd_{2k+j}, k)   (streamed per k)
//
// b kept in log2-space; softmax 1/s never materialized (cancels in squash):
//   out = a * sq * rcp(s^2+sq) * rsq(sq + eps*s^2).   No max-subtract.
//
// Register budget 51 (single accumulation chain pair, streamed agree reduce)
// -> 10 x 128-thread blocks per SM = 40 resident warps (62.5% occupancy).
__global__ void __launch_bounds__(128, 10) routing_kernel(
    const float* __restrict__ pred,
    const float* __restrict__ b_in,
    const int*   __restrict__ nit,
    float*       __restrict__ out,
    int n_loc, int ohw, int ohw_mask)
{
    const int lane = threadIdx.x & 31;
    const int t = lane & 7;
    const int h = t >> 2;
    const int q = t & 3;
    const int g = lane >> 3;
    const unsigned w = blockIdx.x * (blockDim.x >> 5) + (threadIdx.x >> 5);
    if (w * 4u >= (unsigned)n_loc) return;      // warp-uniform guard
    const unsigned loc = w * 4u + g;

    // ---- pred tile: 8 coalesced LDG.128, XOR-ordered rows ----
    const ulonglong2* pp =
        reinterpret_cast<const ulonglong2*>(pred) + (size_t)w * 256;
    Row P[8];
    {
        const int base = 64 * g + 32 * h + q;
#pragma unroll
        for (int k = 0; k < 4; ++k) {
            const int off = 8 * (q ^ k);
            P[2 * k].u     = pp[base + off];
            P[2 * k + 1].u = pp[base + off + 4];
        }
    }

    // ---- owned rows' logits: one LDG.64 (log2-space) ----
    const unsigned bloc = ohw_mask ? (loc & (unsigned)ohw_mask)
                                   : (loc % (unsigned)ohw);
    float bb0, bb1;
    {
        const float2 b2 = *reinterpret_cast<const float2*>(
            b_in + (size_t)bloc * 16 + 8 * h + 2 * q);
        bb0 = b2.x * LOG2E;
        bb1 = b2.y * LOG2E;
    }

    const int iters = *nit;
    float o0, o1, o2, o3;

    auto pass = [&]() {
        const float e0 = ex2f(bb0), e1 = ex2f(bb1);

        // k=0: own rows
        u64 a01 = fma2(bcast2(e0), P[0].u.x, 0ull);
        u64 a23 = fma2(bcast2(e0), P[0].u.y, 0ull);
        a01 = fma2(bcast2(e1), P[1].u.x, a01);
        a23 = fma2(bcast2(e1), P[1].u.y, a23);
        float s = e0 + e1;

        // k=1..3: gathered via shfl.xor, consumed immediately (low pressure)
#pragma unroll
        for (int k = 1; k < 4; ++k) {
            const float ea = __shfl_xor_sync(FULLMASK, e0, k, 4);
            const float eb = __shfl_xor_sync(FULLMASK, e1, k, 4);
            a01 = fma2(bcast2(ea), P[2 * k].u.x, a01);
            a23 = fma2(bcast2(ea), P[2 * k].u.y, a23);
            a01 = fma2(bcast2(eb), P[2 * k + 1].u.x, a01);
            a23 = fma2(bcast2(eb), P[2 * k + 1].u.y, a23);
            s += ea + eb;
        }

        // other row-half (xor 4)
        s += __shfl_xor_sync(FULLMASK, s, 4);
        a01 = add2(a01, __shfl_xor_sync(FULLMASK, a01, 4));
        a23 = add2(a23, __shfl_xor_sync(FULLMASK, a23, 4));

        const float2 lo = unpk(a01), hi = unpk(a23);
        const float a0 = lo.x, a1 = lo.y, a2 = hi.x, a3 = hi.y;

        // |a|^2 over 16 d: local quad + d-reduce over q
        float sq = fmaf(a3, a3, fmaf(a2, a2, fmaf(a1, a1, a0 * a0)));
        sq += __shfl_xor_sync(FULLMASK, sq, 1);
        sq += __shfl_xor_sync(FULLMASK, sq, 2);

        // folded squash: 2 MUFU, softmax 1/s fully cancelled
        const float s2 = s * s;
        const float f  = sq * rcpf(s2 + sq) * rsqf(fmaf(1e-7f, s2, sq));
        o0 = a0 * f; o1 = a1 * f; o2 = a2 * f; o3 = a3 * f;
    };

    pass();
    for (int it = 0; it < iters; ++it) {
        // streamed xor ring-reduce: compute slot pair for k, exchange at once
        float p0 = fmaf(P[0].f.w, o3, fmaf(P[0].f.z, o2,
                   fmaf(P[0].f.y, o1, P[0].f.x * o0)));
        float p1 = fmaf(P[1].f.w, o3, fmaf(P[1].f.z, o2,
                   fmaf(P[1].f.y, o1, P[1].f.x * o0)));
#pragma unroll
        for (int k = 1; k < 4; ++k) {
            const float t0 = fmaf(P[2*k].f.w, o3, fmaf(P[2*k].f.z, o2,
                             fmaf(P[2*k].f.y, o1, P[2*k].f.x * o0)));
            const float t1 = fmaf(P[2*k+1].f.w, o3, fmaf(P[2*k+1].f.z, o2,
                             fmaf(P[2*k+1].f.y, o1, P[2*k+1].f.x * o0)));
            p0 += __shfl_xor_sync(FULLMASK, t0, k, 4);
            p1 += __shfl_xor_sync(FULLMASK, t1, k, 4);
        }
        bb0 = fmaf(p0, LOG2E, bb0);
        bb1 = fmaf(p1, LOG2E, bb1);
        pass();
    }

    if (h == 0)
        reinterpret_cast<float4*>(out)[(size_t)loc * 4 + q] =
            make_float4(o0, o1, o2, o3);
}

extern "C" void kernel_launch(void* const* d_in, const int* in_sizes, int n_in,
                              void* d_out, int out_size) {
    const float* pred = (const float*)d_in[0];
    const float* b    = (const float*)d_in[1];
    const int*   nit  = (const int*)d_in[2];
    float* out = (float*)d_out;

    const int n_loc = in_sizes[0] / 256;   // B*O*H*W
    const int ohw   = in_sizes[1] / 16;    // O*H*W
    const int ohw_mask = ((ohw & (ohw - 1)) == 0) ? (ohw - 1) : 0;

    const int warps  = (n_loc + 3) / 4;    // 4 locations per warp
    const int blocks = (warps + 3) / 4;    // 4 warps per block (128 threads)
    routing_kernel<<<blocks, 128>>>(pred, b, nit, out, n_loc, ohw, ohw_mask);
}